// round 9
// baseline (speedup 1.0000x reference)
#include <cuda_runtime.h>
#include <cuda_bf16.h>
#include <stdint.h>

#define NN 100000
#define NR 100032                   // NN rounded up to 64
#define NE 600000
#define HD 128
#define NL 6
#define NG 1024
#define NT64 (NR / 64)              // 1563 tiles of 64 rows
#define SCAN_BLOCKS 98
#define PAD 136                     // bf16 elems per smem row (272B)

// ---------------- device scratch ----------------
__device__ float g_h[NN * HD];                      // hidden state between layers (fp32)
__device__ __align__(16) __nv_bfloat16 g_zhi[NR * HD];   // aggregated input, hi plane
__device__ __align__(16) __nv_bfloat16 g_zlo[NR * HD];   // lo plane
__device__ __align__(16) __nv_bfloat16 g_z1hi[NR * HD];  // mid activation, hi plane
__device__ __align__(16) __nv_bfloat16 g_z1lo[NR * HD];  // lo plane
__device__ int g_cnt[NN];
__device__ int g_cur[NN];
__device__ int g_off[NN + 1];
__device__ int g_srclist[NE];
__device__ int g_bsum[SCAN_BLOCKS];
// per layer: [W1hi, W1lo, W2hi, W2lo], each [n][k]
__device__ __align__(16) __nv_bfloat16 g_wsplit[NL][4][HD * HD];

// ---------------- PTX helpers ----------------
__device__ __forceinline__ void mma_bf16(float* d, const uint32_t* a, const uint32_t* b) {
    asm volatile(
        "mma.sync.aligned.m16n8k16.row.col.f32.bf16.bf16.f32 "
        "{%0,%1,%2,%3}, {%4,%5,%6,%7}, {%8,%9}, {%0,%1,%2,%3};\n"
        : "+f"(d[0]), "+f"(d[1]), "+f"(d[2]), "+f"(d[3])
        : "r"(a[0]), "r"(a[1]), "r"(a[2]), "r"(a[3]), "r"(b[0]), "r"(b[1]));
}
#define LDSM4(r0, r1, r2, r3, addr) \
    asm volatile("ldmatrix.sync.aligned.m8n8.x4.shared.b16 {%0,%1,%2,%3}, [%4];" \
                 : "=r"(r0), "=r"(r1), "=r"(r2), "=r"(r3) : "r"(addr))
__device__ __forceinline__ uint32_t s2u(const void* p) {
    return (uint32_t)__cvta_generic_to_shared(p);
}
__device__ __forceinline__ void cp16(uint32_t dst, const void* src) {
    asm volatile("cp.async.ca.shared.global [%0], [%1], 16;\n" :: "r"(dst), "l"(src));
}
__device__ __forceinline__ void cp_commit_wait() {
    asm volatile("cp.async.commit_group;\n");
    asm volatile("cp.async.wait_group 0;\n" ::: "memory");
}

// ---------------- weight prep ----------------
__global__ void k_prep_weights(const float* __restrict__ W1, const float* __restrict__ W2) {
    int idx = blockIdx.x * blockDim.x + threadIdx.x;
    if (idx >= NL * HD * HD) return;
    int l = idx / (HD * HD);
    int rem = idx % (HD * HD);
    int k = rem / HD;
    int n = rem % HD;
#pragma unroll
    for (int m = 0; m < 2; m++) {
        float w = (m ? W2 : W1)[idx];
        __nv_bfloat16 hi = __float2bfloat16(w);
        __nv_bfloat16 lo = __float2bfloat16(w - __bfloat162float(hi));
        g_wsplit[l][m * 2][n * HD + k] = hi;
        g_wsplit[l][m * 2 + 1][n * HD + k] = lo;
    }
}

// ---------------- CSR build (by dst) ----------------
__global__ void k_zero() {
    int i = blockIdx.x * blockDim.x + threadIdx.x;
    if (i < NN) { g_cnt[i] = 0; g_cur[i] = 0; }
}
__global__ void k_count(const int* __restrict__ edge) {
    int e = blockIdx.x * blockDim.x + threadIdx.x;
    if (e < NE) atomicAdd(&g_cnt[edge[NE + e]], 1);
}
__global__ void k_scan1() {
    __shared__ int s[1024];
    int t = threadIdx.x;
    int i = blockIdx.x * 1024 + t;
    int v = (i < NN) ? g_cnt[i] : 0;
    s[t] = v;
    __syncthreads();
    for (int d = 1; d < 1024; d <<= 1) {
        int x = (t >= d) ? s[t - d] : 0;
        __syncthreads();
        s[t] += x;
        __syncthreads();
    }
    if (i <= NN) g_off[i] = s[t] - v;
    if (t == 1023) g_bsum[blockIdx.x] = s[1023];
}
__global__ void k_scan2() {
    if (threadIdx.x == 0) {
        int acc = 0;
        for (int i = 0; i < SCAN_BLOCKS; i++) { int v = g_bsum[i]; g_bsum[i] = acc; acc += v; }
    }
}
__global__ void k_scan3() {
    int i = blockIdx.x * 1024 + threadIdx.x;
    if (i <= NN) g_off[i] += g_bsum[blockIdx.x];
}
__global__ void k_fill(const int* __restrict__ edge) {
    int e = blockIdx.x * blockDim.x + threadIdx.x;
    if (e < NE) {
        int d = edge[NE + e];
        int p = atomicAdd(&g_cur[d], 1);
        g_srclist[g_off[d] + p] = edge[e];
    }
}

// ---------------- gather: z = h + sum_{j->i} h[j], written as bf16 hi/lo planes ----------------
__global__ void k_gather(const float* __restrict__ xin, int first) {
    const float* h = first ? xin : (const float*)g_h;
    int w = (blockIdx.x * blockDim.x + threadIdx.x) >> 5;
    int lane = threadIdx.x & 31;
    if (w >= NN) return;
    int beg = g_off[w], end = g_off[w + 1];
    const float4* hv = (const float4*)h;
    float4 acc = hv[(size_t)w * 32 + lane];
    int e = beg;
    for (; e + 4 <= end; e += 4) {
        int s0 = g_srclist[e],     s1 = g_srclist[e + 1];
        int s2 = g_srclist[e + 2], s3 = g_srclist[e + 3];
        float4 v0 = __ldg(&hv[(size_t)s0 * 32 + lane]);
        float4 v1 = __ldg(&hv[(size_t)s1 * 32 + lane]);
        float4 v2 = __ldg(&hv[(size_t)s2 * 32 + lane]);
        float4 v3 = __ldg(&hv[(size_t)s3 * 32 + lane]);
        acc.x += v0.x + v1.x + v2.x + v3.x;
        acc.y += v0.y + v1.y + v2.y + v3.y;
        acc.z += v0.z + v1.z + v2.z + v3.z;
        acc.w += v0.w + v1.w + v2.w + v3.w;
    }
    for (; e < end; e++) {
        float4 v = __ldg(&hv[(size_t)g_srclist[e] * 32 + lane]);
        acc.x += v.x; acc.y += v.y; acc.z += v.z; acc.w += v.w;
    }
    __nv_bfloat16 h0 = __float2bfloat16(acc.x), h1 = __float2bfloat16(acc.y);
    __nv_bfloat16 h2 = __float2bfloat16(acc.z), h3 = __float2bfloat16(acc.w);
    __nv_bfloat162 hp0 = __halves2bfloat162(h0, h1);
    __nv_bfloat162 hp1 = __halves2bfloat162(h2, h3);
    __nv_bfloat162 lp0 = __floats2bfloat162_rn(acc.x - __bfloat162float(h0), acc.y - __bfloat162float(h1));
    __nv_bfloat162 lp1 = __floats2bfloat162_rn(acc.z - __bfloat162float(h2), acc.w - __bfloat162float(h3));
    ((uint2*)g_zhi)[(size_t)w * 32 + lane] = make_uint2(*(uint32_t*)&hp0, *(uint32_t*)&hp1);
    ((uint2*)g_zlo)[(size_t)w * 32 + lane] = make_uint2(*(uint32_t*)&lp0, *(uint32_t*)&lp1);
}

// ---------------- one-GEMM kernel: out = relu(A @ W + b), bf16x3, 64-row tiles, occ 2 ----------------
// smem: Ahi[64][PAD], Alo[64][PAD], Whi[128][PAD], Wlo[128][PAD] = 104,448 B
#define SM_GEMM ((64 + 64 + 128 + 128) * PAD * 2)

__global__ void __launch_bounds__(256, 2) k_gemm(
    const __nv_bfloat16* __restrict__ Whi_g, const __nv_bfloat16* __restrict__ Wlo_g,
    const __nv_bfloat16* __restrict__ Ahi_g, const __nv_bfloat16* __restrict__ Alo_g,
    const float* __restrict__ bias,
    int mode,                                   // 0: bf16 planes out (Ohi/Olo); 1: fp32 out (Of, guard NN)
    __nv_bfloat16* __restrict__ Ohi, __nv_bfloat16* __restrict__ Olo,
    float* __restrict__ Of)
{
    extern __shared__ __nv_bfloat16 sm[];
    __nv_bfloat16* Ahi = sm;
    __nv_bfloat16* Alo = sm + 64 * PAD;
    __nv_bfloat16* Whi = sm + 128 * PAD;
    __nv_bfloat16* Wlo = sm + 256 * PAD;

    int tid = threadIdx.x, lane = tid & 31, warp = tid >> 5;
    int wr = warp & 3, wc = warp >> 2;   // warp tile: rows wr*16..+15, cols wc*64..+63

    uint32_t sAhiB = s2u(Ahi), sAloB = s2u(Alo);
    uint32_t sWhiB = s2u(Whi), sWloB = s2u(Wlo);

    // stage weights via cp.async: 128 rows x 16 chunks x 2 planes
    for (int i = tid; i < 4096; i += 256) {
        int plane = i >> 11, rem = i & 2047;
        int r = rem >> 4, c = rem & 15;
        uint32_t dst = (plane ? sWloB : sWhiB) + (uint32_t)(r * PAD + c * 8) * 2;
        const __nv_bfloat16* src = (plane ? Wlo_g : Whi_g) + r * HD + c * 8;
        cp16(dst, src);
    }

    // bias registers
    float bv[16];
    int cb = wc * 64 + (lane & 3) * 2;
#pragma unroll
    for (int nt = 0; nt < 8; nt++) {
        bv[nt * 2]     = __ldg(&bias[cb + nt * 8]);
        bv[nt * 2 + 1] = __ldg(&bias[cb + nt * 8 + 1]);
    }
    cp_commit_wait();
    __syncthreads();

    // ldmatrix source addresses
    int g = lane >> 3, lr = lane & 7;
    int arow = wr * 16 + (g & 1) * 8 + lr;
    int akg  = (g >> 1) * 8;
    int brow = wc * 64 + (g >> 1) * 8 + lr;
    int bkg  = (g & 1) * 8;
    uint32_t aoff = (uint32_t)(arow * PAD + akg) * 2;
    uint32_t boff = (uint32_t)(brow * PAD + bkg) * 2;

    for (int tile = blockIdx.x; tile < NT64; tile += gridDim.x) {
        int row0 = tile * 64;

        // ---- cp.async A tile: 64 rows x 16 chunks x 2 planes ----
        for (int i = tid; i < 2048; i += 256) {
            int plane = i >> 10, rem = i & 1023;
            int r = rem >> 4, c = rem & 15;
            uint32_t dst = (plane ? sAloB : sAhiB) + (uint32_t)(r * PAD + c * 8) * 2;
            const __nv_bfloat16* src = (plane ? Alo_g : Ahi_g) + (size_t)(row0 + r) * HD + c * 8;
            cp16(dst, src);
        }
        cp_commit_wait();
        __syncthreads();

        // ---- GEMM bf16x3: acc = A @ W ----
        float acc[8][4];
#pragma unroll
        for (int nt = 0; nt < 8; nt++)
#pragma unroll
            for (int j = 0; j < 4; j++) acc[nt][j] = 0.f;

#pragma unroll
        for (int term = 0; term < 3; term++) {
            uint32_t sA = ((term == 2) ? sAloB : sAhiB) + aoff;
            uint32_t sB = ((term == 1) ? sWloB : sWhiB) + boff;
#pragma unroll
            for (int ks = 0; ks < 8; ks++) {
                uint32_t ko = (uint32_t)(ks * 16) * 2;
                uint32_t a[4], b[8][2];
                LDSM4(a[0], a[1], a[2], a[3], sA + ko);
#pragma unroll
                for (int j = 0; j < 4; j++)
                    LDSM4(b[2 * j][0], b[2 * j][1], b[2 * j + 1][0], b[2 * j + 1][1],
                          sB + ko + (uint32_t)(16 * j) * PAD * 2u);
#pragma unroll
                for (int nt = 0; nt < 8; nt++)
                    mma_bf16(acc[nt], a, b[nt]);
            }
        }
        __syncthreads();   // A reads done before next tile's cp.async overwrites

        // ---- epilogue ----
        int r0 = row0 + wr * 16 + (lane >> 2);
        int r1 = r0 + 8;
        if (mode == 0) {
#pragma unroll
            for (int nt = 0; nt < 8; nt++) {
                int c = wc * 64 + nt * 8 + (lane & 3) * 2;
                float v0 = fmaxf(acc[nt][0] + bv[nt * 2],     0.f);
                float v1 = fmaxf(acc[nt][1] + bv[nt * 2 + 1], 0.f);
                float v2 = fmaxf(acc[nt][2] + bv[nt * 2],     0.f);
                float v3 = fmaxf(acc[nt][3] + bv[nt * 2 + 1], 0.f);
                __nv_bfloat16 h0 = __float2bfloat16(v0), h1 = __float2bfloat16(v1);
                __nv_bfloat16 h2 = __float2bfloat16(v2), h3 = __float2bfloat16(v3);
                __nv_bfloat162 hp0 = __halves2bfloat162(h0, h1);
                __nv_bfloat162 hp1 = __halves2bfloat162(h2, h3);
                __nv_bfloat162 lp0 = __floats2bfloat162_rn(v0 - __bfloat162float(h0), v1 - __bfloat162float(h1));
                __nv_bfloat162 lp1 = __floats2bfloat162_rn(v2 - __bfloat162float(h2), v3 - __bfloat162float(h3));
                *(uint32_t*)&Ohi[(size_t)r0 * HD + c] = *(uint32_t*)&hp0;
                *(uint32_t*)&Olo[(size_t)r0 * HD + c] = *(uint32_t*)&lp0;
                *(uint32_t*)&Ohi[(size_t)r1 * HD + c] = *(uint32_t*)&hp1;
                *(uint32_t*)&Olo[(size_t)r1 * HD + c] = *(uint32_t*)&lp1;
            }
        } else {
#pragma unroll
            for (int nt = 0; nt < 8; nt++) {
                int c = wc * 64 + nt * 8 + (lane & 3) * 2;
                if (r0 < NN) {
                    float2 v;
                    v.x = fmaxf(acc[nt][0] + bv[nt * 2],     0.f);
                    v.y = fmaxf(acc[nt][1] + bv[nt * 2 + 1], 0.f);
                    ((float2*)Of)[(size_t)r0 * 64 + (c >> 1)] = v;
                }
                if (r1 < NN) {
                    float2 v;
                    v.x = fmaxf(acc[nt][2] + bv[nt * 2],     0.f);
                    v.y = fmaxf(acc[nt][3] + bv[nt * 2 + 1], 0.f);
                    ((float2*)Of)[(size_t)r1 * 64 + (c >> 1)] = v;
                }
            }
        }
    }
}

// ---------------- mean pool per graph (batch is sorted) ----------------
__global__ void k_pool(const float* __restrict__ xout, const int* __restrict__ batch,
                       float* __restrict__ gout) {
    int b = blockIdx.x, t = threadIdx.x;
    int lo = 0, hi = NN;
    while (lo < hi) { int m = (lo + hi) >> 1; if (batch[m] < b) lo = m + 1; else hi = m; }
    int beg = lo;
    hi = NN;
    while (lo < hi) { int m = (lo + hi) >> 1; if (batch[m] <= b) lo = m + 1; else hi = m; }
    int end = lo;
    float acc = 0.f;
    for (int i = beg; i < end; i++) acc += xout[(size_t)i * HD + t];
    int cnt = end - beg;
    gout[b * HD + t] = acc / (float)(cnt > 0 ? cnt : 1);
}

// ---------------- launch ----------------
extern "C" void kernel_launch(void* const* d_in, const int* in_sizes, int n_in,
                              void* d_out, int out_size)
{
    const float* x   = (const float*)d_in[0];
    const int* edge  = (const int*)d_in[1];
    const int* batch = (const int*)d_in[2];
    const float* W1  = (const float*)d_in[3];
    const float* b1  = (const float*)d_in[4];
    const float* W2  = (const float*)d_in[5];
    const float* b2  = (const float*)d_in[6];
    float* out  = (float*)d_out;
    float* xout = out;
    float* gout = out + (size_t)NN * HD;

    cudaFuncSetAttribute(k_gemm, cudaFuncAttributeMaxDynamicSharedMemorySize, SM_GEMM);

    k_prep_weights<<<(NL * HD * HD + 255) / 256, 256>>>(W1, W2);
    k_zero<<<(NN + 255) / 256, 256>>>();
    k_count<<<(NE + 255) / 256, 256>>>(edge);
    k_scan1<<<SCAN_BLOCKS, 1024>>>();
    k_scan2<<<1, 32>>>();
    k_scan3<<<SCAN_BLOCKS, 1024>>>();
    k_fill<<<(NE + 255) / 256, 256>>>(edge);

    __nv_bfloat16 *zhi, *zlo, *z1hi, *z1lo, *wsp;
    float* hbuf;
    cudaGetSymbolAddress((void**)&zhi,  g_zhi);
    cudaGetSymbolAddress((void**)&zlo,  g_zlo);
    cudaGetSymbolAddress((void**)&z1hi, g_z1hi);
    cudaGetSymbolAddress((void**)&z1lo, g_z1lo);
    cudaGetSymbolAddress((void**)&wsp,  g_wsplit);
    cudaGetSymbolAddress((void**)&hbuf, g_h);

    for (int l = 0; l < NL; l++) {
        const __nv_bfloat16* w = wsp + (size_t)l * 4 * HD * HD;
        k_gather<<<(NN * 32 + 255) / 256, 256>>>(x, l == 0 ? 1 : 0);
        k_gemm<<<296, 256, SM_GEMM>>>(w, w + HD * HD, zhi, zlo,
                                      b1 + (size_t)l * HD, 0, z1hi, z1lo, (float*)0);
        k_gemm<<<296, 256, SM_GEMM>>>(w + 2 * HD * HD, w + 3 * HD * HD, z1hi, z1lo,
                                      b2 + (size_t)l * HD, 1, (__nv_bfloat16*)0, (__nv_bfloat16*)0,
                                      (l == NL - 1) ? xout : hbuf);
    }
    k_pool<<<NG, HD>>>(xout, batch, gout);
}

// round 10
// speedup vs baseline: 1.2829x; 1.2829x over previous
#include <cuda_runtime.h>
#include <cuda_bf16.h>
#include <stdint.h>

#define NN 100000
#define NR 100096                   // NN rounded up to 128
#define NE 600000
#define HD 128
#define NL 6
#define NG 1024
#define NTILES (NR / 128)           // 782
#define SCAN_BLOCKS 98
#define PAD 136                     // bf16 elems per smem row (272B, conflict-free)

// ---------------- device scratch ----------------
__device__ float g_h[NN * HD];                           // hidden state between layers (fp32)
__device__ __align__(16) __nv_bfloat16 g_zhi[NR * HD];   // aggregated input, hi plane (rows >= NN stay 0)
__device__ __align__(16) __nv_bfloat16 g_zlo[NR * HD];   // lo plane
__device__ int g_cnt[NN];
__device__ int g_cur[NN];
__device__ int g_off[NN + 1];
__device__ int g_srclist[NE];
__device__ int g_bsum[SCAN_BLOCKS];
// per layer: [W1hi, W1lo, W2hi, W2lo], each [n][k]
__device__ __align__(16) __nv_bfloat16 g_wsplit[NL][4][HD * HD];

// ---------------- PTX helpers ----------------
__device__ __forceinline__ void mma_bf16(float* d, const uint32_t* a, const uint32_t* b) {
    asm volatile(
        "mma.sync.aligned.m16n8k16.row.col.f32.bf16.bf16.f32 "
        "{%0,%1,%2,%3}, {%4,%5,%6,%7}, {%8,%9}, {%0,%1,%2,%3};\n"
        : "+f"(d[0]), "+f"(d[1]), "+f"(d[2]), "+f"(d[3])
        : "r"(a[0]), "r"(a[1]), "r"(a[2]), "r"(a[3]), "r"(b[0]), "r"(b[1]));
}
#define LDSM4(r0, r1, r2, r3, addr) \
    asm volatile("ldmatrix.sync.aligned.m8n8.x4.shared.b16 {%0,%1,%2,%3}, [%4];" \
                 : "=r"(r0), "=r"(r1), "=r"(r2), "=r"(r3) : "r"(addr))
__device__ __forceinline__ uint32_t s2u(const void* p) {
    return (uint32_t)__cvta_generic_to_shared(p);
}
__device__ __forceinline__ void cp16(uint32_t dst, const void* src) {
    asm volatile("cp.async.ca.shared.global [%0], [%1], 16;\n" :: "r"(dst), "l"(src));
}
__device__ __forceinline__ void cp_commit_wait() {
    asm volatile("cp.async.commit_group;\n");
    asm volatile("cp.async.wait_group 0;\n" ::: "memory");
}

// ---------------- weight prep: transpose + bf16 hi/lo split ----------------
__global__ void k_prep_weights(const float* __restrict__ W1, const float* __restrict__ W2) {
    int idx = blockIdx.x * blockDim.x + threadIdx.x;
    if (idx >= NL * HD * HD) return;
    int l = idx / (HD * HD);
    int rem = idx % (HD * HD);
    int k = rem / HD;
    int n = rem % HD;
#pragma unroll
    for (int m = 0; m < 2; m++) {
        float w = (m ? W2 : W1)[idx];
        __nv_bfloat16 hi = __float2bfloat16(w);
        __nv_bfloat16 lo = __float2bfloat16(w - __bfloat162float(hi));
        g_wsplit[l][m * 2][n * HD + k] = hi;
        g_wsplit[l][m * 2 + 1][n * HD + k] = lo;
    }
}

// ---------------- CSR build (by dst) ----------------
__global__ void k_count(const int* __restrict__ edge) {
    int e = blockIdx.x * blockDim.x + threadIdx.x;
    if (e < NE) atomicAdd(&g_cnt[edge[NE + e]], 1);
}
__global__ void k_scan1() {
    __shared__ int s[1024];
    int t = threadIdx.x;
    int i = blockIdx.x * 1024 + t;
    int v = (i < NN) ? g_cnt[i] : 0;
    s[t] = v;
    __syncthreads();
    for (int d = 1; d < 1024; d <<= 1) {
        int x = (t >= d) ? s[t - d] : 0;
        __syncthreads();
        s[t] += x;
        __syncthreads();
    }
    if (i <= NN) g_off[i] = s[t] - v;
    if (t == 1023) g_bsum[blockIdx.x] = s[1023];
}
__global__ void k_scan2() {
    if (threadIdx.x == 0) {
        int acc = 0;
        for (int i = 0; i < SCAN_BLOCKS; i++) { int v = g_bsum[i]; g_bsum[i] = acc; acc += v; }
    }
}
__global__ void k_scan3() {
    int i = blockIdx.x * 1024 + threadIdx.x;
    if (i <= NN) g_off[i] += g_bsum[blockIdx.x];
}
__global__ void k_fill(const int* __restrict__ edge) {
    int e = blockIdx.x * blockDim.x + threadIdx.x;
    if (e < NE) {
        int d = edge[NE + e];
        int p = atomicAdd(&g_cur[d], 1);
        g_srclist[g_off[d] + p] = edge[e];
    }
}

// ---------------- gather: z = h + sum h[src], written as bf16 hi/lo planes ----------------
__global__ void k_gather(const float* __restrict__ xin, int first) {
    const float* h = first ? xin : (const float*)g_h;
    int w = (blockIdx.x * blockDim.x + threadIdx.x) >> 5;
    int lane = threadIdx.x & 31;
    if (w >= NN) return;
    int beg = g_off[w], end = g_off[w + 1];
    const float4* hv = (const float4*)h;
    float4 acc = hv[(size_t)w * 32 + lane];
    int e = beg;
    for (; e + 4 <= end; e += 4) {
        int s0 = g_srclist[e],     s1 = g_srclist[e + 1];
        int s2 = g_srclist[e + 2], s3 = g_srclist[e + 3];
        float4 v0 = __ldg(&hv[(size_t)s0 * 32 + lane]);
        float4 v1 = __ldg(&hv[(size_t)s1 * 32 + lane]);
        float4 v2 = __ldg(&hv[(size_t)s2 * 32 + lane]);
        float4 v3 = __ldg(&hv[(size_t)s3 * 32 + lane]);
        acc.x += v0.x + v1.x + v2.x + v3.x;
        acc.y += v0.y + v1.y + v2.y + v3.y;
        acc.z += v0.z + v1.z + v2.z + v3.z;
        acc.w += v0.w + v1.w + v2.w + v3.w;
    }
    for (; e < end; e++) {
        float4 v = __ldg(&hv[(size_t)g_srclist[e] * 32 + lane]);
        acc.x += v.x; acc.y += v.y; acc.z += v.z; acc.w += v.w;
    }
    __nv_bfloat16 h0 = __float2bfloat16(acc.x), h1 = __float2bfloat16(acc.y);
    __nv_bfloat16 h2 = __float2bfloat16(acc.z), h3 = __float2bfloat16(acc.w);
    __nv_bfloat162 hp0 = __halves2bfloat162(h0, h1);
    __nv_bfloat162 hp1 = __halves2bfloat162(h2, h3);
    __nv_bfloat162 lp0 = __floats2bfloat162_rn(acc.x - __bfloat162float(h0), acc.y - __bfloat162float(h1));
    __nv_bfloat162 lp1 = __floats2bfloat162_rn(acc.z - __bfloat162float(h2), acc.w - __bfloat162float(h3));
    ((uint2*)g_zhi)[(size_t)w * 32 + lane] = make_uint2(*(uint32_t*)&hp0, *(uint32_t*)&hp1);
    ((uint2*)g_zlo)[(size_t)w * 32 + lane] = make_uint2(*(uint32_t*)&lp0, *(uint32_t*)&lp1);
}

// ---------------- fused 2-layer MLP: bf16x3 with single-pass fused terms ----------------
// smem: Ahi[128][PAD], Alo[128][PAD], W[4][128][PAD]
#define SM_TOTAL (6 * 128 * PAD * 2)   // 208,896 bytes

// Fused-term warp-tile GEMM: per k-step load Ah/Al/Bh/Bl once, do 48 MMAs.
__device__ __forceinline__ void gemm_tile_fused(
    uint32_t sAhi, uint32_t sAlo, uint32_t sBhi, uint32_t sBlo,
    float acc[2][8][4])
{
#pragma unroll
    for (int ks = 0; ks < 8; ks++) {
        uint32_t ko = (uint32_t)(ks * 16) * 2;
        uint32_t ah[2][4], al[2][4], bh[8][2], bl[8][2];
        LDSM4(ah[0][0], ah[0][1], ah[0][2], ah[0][3], sAhi + ko);
        LDSM4(ah[1][0], ah[1][1], ah[1][2], ah[1][3], sAhi + ko + 16u * PAD * 2u);
        LDSM4(al[0][0], al[0][1], al[0][2], al[0][3], sAlo + ko);
        LDSM4(al[1][0], al[1][1], al[1][2], al[1][3], sAlo + ko + 16u * PAD * 2u);
#pragma unroll
        for (int j = 0; j < 4; j++) {
            LDSM4(bh[2 * j][0], bh[2 * j][1], bh[2 * j + 1][0], bh[2 * j + 1][1],
                  sBhi + ko + (uint32_t)(16 * j) * PAD * 2u);
            LDSM4(bl[2 * j][0], bl[2 * j][1], bl[2 * j + 1][0], bl[2 * j + 1][1],
                  sBlo + ko + (uint32_t)(16 * j) * PAD * 2u);
        }
#pragma unroll
        for (int mt = 0; mt < 2; mt++)
#pragma unroll
            for (int nt = 0; nt < 8; nt++)
                mma_bf16(acc[mt][nt], ah[mt], bh[nt]);
#pragma unroll
        for (int mt = 0; mt < 2; mt++)
#pragma unroll
            for (int nt = 0; nt < 8; nt++)
                mma_bf16(acc[mt][nt], ah[mt], bl[nt]);
#pragma unroll
        for (int mt = 0; mt < 2; mt++)
#pragma unroll
            for (int nt = 0; nt < 8; nt++)
                mma_bf16(acc[mt][nt], al[mt], bh[nt]);
    }
}

__global__ void __launch_bounds__(256, 1) k_mlp(
    int layer, const float* __restrict__ b1, const float* __restrict__ b2,
    int last, float* __restrict__ xoutp)
{
    extern __shared__ __nv_bfloat16 sm[];
    __nv_bfloat16* Ahi = sm;
    __nv_bfloat16* Alo = sm + 128 * PAD;
    __nv_bfloat16* Wb  = sm + 2 * 128 * PAD;   // [4 mats][128 rows][PAD]
    float* outp = last ? xoutp : (float*)g_h;

    int tid = threadIdx.x, lane = tid & 31, warp = tid >> 5;
    int wr = warp >> 1, wc = warp & 1;   // warp tile: rows wr*32..+31, cols wc*64..+63

    uint32_t sAhiB = s2u(Ahi), sAloB = s2u(Alo);

    // stage this layer's 4 weight images via cp.async (add padding on the fly)
    for (int i = tid; i < 4 * 128 * 16; i += 256) {
        int matrow = i >> 4, q = i & 15;
        cp16(s2u(&Wb[matrow * PAD]) + (uint32_t)q * 16u, &g_wsplit[layer][0][0] + i * 8);
    }

    // per-thread bias registers (columns this thread owns)
    float bv1[16], bv2[16];
    int cb = wc * 64 + (lane & 3) * 2;
#pragma unroll
    for (int nt = 0; nt < 8; nt++) {
        bv1[nt * 2]     = __ldg(&b1[cb + nt * 8]);
        bv1[nt * 2 + 1] = __ldg(&b1[cb + nt * 8 + 1]);
        bv2[nt * 2]     = __ldg(&b2[cb + nt * 8]);
        bv2[nt * 2 + 1] = __ldg(&b2[cb + nt * 8 + 1]);
    }
    cp_commit_wait();
    __syncthreads();

    uint32_t sW1hi = s2u(Wb), sW1lo = s2u(Wb + 128 * PAD);
    uint32_t sW2hi = s2u(Wb + 2 * 128 * PAD), sW2lo = s2u(Wb + 3 * 128 * PAD);

    // ldmatrix per-lane source offsets
    int g = lane >> 3, lr = lane & 7;
    int arow = wr * 32 + (g & 1) * 8 + lr;
    int akg  = (g >> 1) * 8;
    int brow = wc * 64 + (g >> 1) * 8 + lr;
    int bkg  = (g & 1) * 8;
    uint32_t aoff = (uint32_t)(arow * PAD + akg) * 2;
    uint32_t boff = (uint32_t)(brow * PAD + bkg) * 2;

    for (int tile = blockIdx.x; tile < NTILES; tile += gridDim.x) {
        int row0 = tile * 128;

        // ---- cp.async A tile from bf16 planes: 128 rows x 16 chunks x 2 planes ----
        for (int i = tid; i < 4096; i += 256) {
            int plane = i >> 11, rem = i & 2047;
            int r = rem >> 4, c = rem & 15;
            uint32_t dst = (plane ? sAloB : sAhiB) + (uint32_t)(r * PAD + c * 8) * 2;
            const __nv_bfloat16* src = (plane ? g_zlo : g_zhi) + (size_t)(row0 + r) * HD + c * 8;
            cp16(dst, src);
        }
        cp_commit_wait();
        __syncthreads();

        // ---- GEMM1: acc = A @ W1 ----
        float acc[2][8][4];
#pragma unroll
        for (int mt = 0; mt < 2; mt++)
#pragma unroll
            for (int nt = 0; nt < 8; nt++)
#pragma unroll
                for (int j = 0; j < 4; j++) acc[mt][nt][j] = 0.f;
        gemm_tile_fused(sAhiB + aoff, sAloB + aoff, sW1hi + boff, sW1lo + boff, acc);
        __syncthreads();   // all GEMM1 reads of A done before overwrite

        // ---- epilogue1: z1 = relu(acc + b1), re-split into Ahi/Alo ----
#pragma unroll
        for (int mt = 0; mt < 2; mt++) {
            int r0 = wr * 32 + mt * 16 + (lane >> 2);
            int r1 = r0 + 8;
#pragma unroll
            for (int nt = 0; nt < 8; nt++) {
                int c = wc * 64 + nt * 8 + (lane & 3) * 2;
                float v0 = fmaxf(acc[mt][nt][0] + bv1[nt * 2],     0.f);
                float v1 = fmaxf(acc[mt][nt][1] + bv1[nt * 2 + 1], 0.f);
                float v2 = fmaxf(acc[mt][nt][2] + bv1[nt * 2],     0.f);
                float v3 = fmaxf(acc[mt][nt][3] + bv1[nt * 2 + 1], 0.f);
                __nv_bfloat16 h0 = __float2bfloat16(v0), h1 = __float2bfloat16(v1);
                __nv_bfloat16 h2 = __float2bfloat16(v2), h3 = __float2bfloat16(v3);
                __nv_bfloat162 hp0 = __halves2bfloat162(h0, h1);
                __nv_bfloat162 hp1 = __halves2bfloat162(h2, h3);
                __nv_bfloat162 lp0 = __floats2bfloat162_rn(v0 - __bfloat162float(h0), v1 - __bfloat162float(h1));
                __nv_bfloat162 lp1 = __floats2bfloat162_rn(v2 - __bfloat162float(h2), v3 - __bfloat162float(h3));
                *(uint32_t*)&Ahi[r0 * PAD + c] = *(uint32_t*)&hp0;
                *(uint32_t*)&Alo[r0 * PAD + c] = *(uint32_t*)&lp0;
                *(uint32_t*)&Ahi[r1 * PAD + c] = *(uint32_t*)&hp1;
                *(uint32_t*)&Alo[r1 * PAD + c] = *(uint32_t*)&lp1;
            }
        }
        __syncthreads();

        // ---- GEMM2: acc = z1 @ W2 ----
#pragma unroll
        for (int mt = 0; mt < 2; mt++)
#pragma unroll
            for (int nt = 0; nt < 8; nt++)
#pragma unroll
                for (int j = 0; j < 4; j++) acc[mt][nt][j] = 0.f;
        gemm_tile_fused(sAhiB + aoff, sAloB + aoff, sW2hi + boff, sW2lo + boff, acc);
        __syncthreads();   // all GEMM2 reads done before next tile's cp.async overwrite

        // ---- epilogue2: h = relu(acc + b2) -> global fp32 ----
#pragma unroll
        for (int mt = 0; mt < 2; mt++) {
            int r0 = row0 + wr * 32 + mt * 16 + (lane >> 2);
            int r1 = r0 + 8;
#pragma unroll
            for (int nt = 0; nt < 8; nt++) {
                int c = wc * 64 + nt * 8 + (lane & 3) * 2;
                if (r0 < NN) {
                    float2 v;
                    v.x = fmaxf(acc[mt][nt][0] + bv2[nt * 2],     0.f);
                    v.y = fmaxf(acc[mt][nt][1] + bv2[nt * 2 + 1], 0.f);
                    ((float2*)outp)[(size_t)r0 * 64 + (c >> 1)] = v;
                }
                if (r1 < NN) {
                    float2 v;
                    v.x = fmaxf(acc[mt][nt][2] + bv2[nt * 2],     0.f);
                    v.y = fmaxf(acc[mt][nt][3] + bv2[nt * 2 + 1], 0.f);
                    ((float2*)outp)[(size_t)r1 * 64 + (c >> 1)] = v;
                }
            }
        }
    }
}

// ---------------- mean pool per graph (batch is sorted) ----------------
__global__ void k_pool(const float* __restrict__ xout, const int* __restrict__ batch,
                       float* __restrict__ gout) {
    int b = blockIdx.x, t = threadIdx.x;
    int lo = 0, hi = NN;
    while (lo < hi) { int m = (lo + hi) >> 1; if (batch[m] < b) lo = m + 1; else hi = m; }
    int beg = lo;
    hi = NN;
    while (lo < hi) { int m = (lo + hi) >> 1; if (batch[m] <= b) lo = m + 1; else hi = m; }
    int end = lo;
    float acc = 0.f;
    for (int i = beg; i < end; i++) acc += xout[(size_t)i * HD + t];
    int cnt = end - beg;
    gout[b * HD + t] = acc / (float)(cnt > 0 ? cnt : 1);
}

// ---------------- launch ----------------
extern "C" void kernel_launch(void* const* d_in, const int* in_sizes, int n_in,
                              void* d_out, int out_size)
{
    const float* x   = (const float*)d_in[0];
    const int* edge  = (const int*)d_in[1];
    const int* batch = (const int*)d_in[2];
    const float* W1  = (const float*)d_in[3];
    const float* b1  = (const float*)d_in[4];
    const float* W2  = (const float*)d_in[5];
    const float* b2  = (const float*)d_in[6];
    float* out  = (float*)d_out;
    float* xout = out;
    float* gout = out + (size_t)NN * HD;

    cudaFuncSetAttribute(k_mlp, cudaFuncAttributeMaxDynamicSharedMemorySize, SM_TOTAL);

    void *cntp, *curp;
    cudaGetSymbolAddress(&cntp, g_cnt);
    cudaGetSymbolAddress(&curp, g_cur);

    k_prep_weights<<<(NL * HD * HD + 255) / 256, 256>>>(W1, W2);
    cudaMemsetAsync(cntp, 0, NN * sizeof(int));
    cudaMemsetAsync(curp, 0, NN * sizeof(int));
    k_count<<<(NE + 255) / 256, 256>>>(edge);
    k_scan1<<<SCAN_BLOCKS, 1024>>>();
    k_scan2<<<1, 32>>>();
    k_scan3<<<SCAN_BLOCKS, 1024>>>();
    k_fill<<<(NE + 255) / 256, 256>>>(edge);

    for (int l = 0; l < NL; l++) {
        k_gather<<<(NN * 32 + 255) / 256, 256>>>(x, l == 0 ? 1 : 0);
        k_mlp<<<148, 256, SM_TOTAL>>>(l, b1 + (size_t)l * HD, b2 + (size_t)l * HD,
                                      (l == NL - 1) ? 1 : 0, xout);
    }
    k_pool<<<NG, HD>>>(xout, batch, gout);
}

// round 11
// speedup vs baseline: 1.3943x; 1.0869x over previous
#include <cuda_runtime.h>
#include <cuda_bf16.h>
#include <stdint.h>

#define NN 100000
#define NR 100096                   // NN rounded up to 128
#define NE 600000
#define HD 128
#define NL 6
#define NG 1024
#define NT64 (NR / 64)              // 1564 tiles of 64 rows
#define GRID 148
#define SCAN_BLOCKS 98

// ---------------- device scratch ----------------
__device__ float g_h[NN * HD];                           // hidden state between layers (fp32)
__device__ __align__(16) __nv_bfloat16 g_zhi[NR * HD];   // aggregated input, hi plane (rows >= NN stay 0)
__device__ __align__(16) __nv_bfloat16 g_zlo[NR * HD];   // lo plane
__device__ int g_cnt[NN];
__device__ int g_cur[NN];
__device__ int g_off[NN + 1];
__device__ int g_srclist[NE];
__device__ int g_bsum[SCAN_BLOCKS];
// per layer: [W1hi, W1lo, W2hi, W2lo], each [n][k] dense 128x128
__device__ __align__(16) __nv_bfloat16 g_wsplit[NL][4][HD * HD];

// ---------------- PTX helpers ----------------
__device__ __forceinline__ void mma_bf16(float* d, const uint32_t* a, const uint32_t* b) {
    asm volatile(
        "mma.sync.aligned.m16n8k16.row.col.f32.bf16.bf16.f32 "
        "{%0,%1,%2,%3}, {%4,%5,%6,%7}, {%8,%9}, {%0,%1,%2,%3};\n"
        : "+f"(d[0]), "+f"(d[1]), "+f"(d[2]), "+f"(d[3])
        : "r"(a[0]), "r"(a[1]), "r"(a[2]), "r"(a[3]), "r"(b[0]), "r"(b[1]));
}
#define LDSM4(r0, r1, r2, r3, addr) \
    asm volatile("ldmatrix.sync.aligned.m8n8.x4.shared.b16 {%0,%1,%2,%3}, [%4];" \
                 : "=r"(r0), "=r"(r1), "=r"(r2), "=r"(r3) : "r"(addr))
__device__ __forceinline__ uint32_t s2u(const void* p) {
    return (uint32_t)__cvta_generic_to_shared(p);
}
__device__ __forceinline__ void cp16(uint32_t dst, const void* src) {
    asm volatile("cp.async.ca.shared.global [%0], [%1], 16;\n" :: "r"(dst), "l"(src));
}
__device__ __forceinline__ void cp_commit() {
    asm volatile("cp.async.commit_group;\n");
}
__device__ __forceinline__ void cp_wait0() {
    asm volatile("cp.async.wait_group 0;\n" ::: "memory");
}

// swizzled byte offset of 16B chunk (r, c) in a plane of 256B rows (16 chunks/row)
__device__ __forceinline__ uint32_t swz(uint32_t r, uint32_t c) {
    return (r * 16 + (c ^ (r & 7))) * 16;
}

// smem byte-offset map (total 229,376 B)
#define OFF_A(buf, plane) ((uint32_t)(((buf) * 2 + (plane)) * 16384))
#define OFF_Z1(plane)     ((uint32_t)(65536 + (plane) * 16384))
#define OFF_W(mat)        ((uint32_t)(98304 + (mat) * 32768))
#define SM_TOTAL          229376

// ---------------- weight prep: transpose + bf16 hi/lo split ----------------
__global__ void k_prep_weights(const float* __restrict__ W1, const float* __restrict__ W2) {
    int idx = blockIdx.x * blockDim.x + threadIdx.x;
    if (idx >= NL * HD * HD) return;
    int l = idx / (HD * HD);
    int rem = idx % (HD * HD);
    int k = rem / HD;
    int n = rem % HD;
#pragma unroll
    for (int m = 0; m < 2; m++) {
        float w = (m ? W2 : W1)[idx];
        __nv_bfloat16 hi = __float2bfloat16(w);
        __nv_bfloat16 lo = __float2bfloat16(w - __bfloat162float(hi));
        g_wsplit[l][m * 2][n * HD + k] = hi;
        g_wsplit[l][m * 2 + 1][n * HD + k] = lo;
    }
}

// ---------------- CSR build (by dst) ----------------
__global__ void k_count(const int* __restrict__ edge) {
    int e = blockIdx.x * blockDim.x + threadIdx.x;
    if (e < NE) atomicAdd(&g_cnt[edge[NE + e]], 1);
}
__global__ void k_scan1() {
    __shared__ int s[1024];
    int t = threadIdx.x;
    int i = blockIdx.x * 1024 + t;
    int v = (i < NN) ? g_cnt[i] : 0;
    s[t] = v;
    __syncthreads();
    for (int d = 1; d < 1024; d <<= 1) {
        int x = (t >= d) ? s[t - d] : 0;
        __syncthreads();
        s[t] += x;
        __syncthreads();
    }
    if (i <= NN) g_off[i] = s[t] - v;
    if (t == 1023) g_bsum[blockIdx.x] = s[1023];
}
__global__ void k_scan2() {   // 32-thread shuffle scan (was 8.2us serial)
    int t = threadIdx.x;
    int carry = 0;
    for (int base = 0; base < SCAN_BLOCKS; base += 32) {
        int i = base + t;
        int orig = (i < SCAN_BLOCKS) ? g_bsum[i] : 0;
        int v = orig;
#pragma unroll
        for (int d = 1; d < 32; d <<= 1) {
            int x = __shfl_up_sync(0xFFFFFFFFu, v, d);
            if (t >= d) v += x;
        }
        if (i < SCAN_BLOCKS) g_bsum[i] = carry + v - orig;
        carry += __shfl_sync(0xFFFFFFFFu, v, 31);
    }
}
__global__ void k_scan3() {
    int i = blockIdx.x * 1024 + threadIdx.x;
    if (i <= NN) g_off[i] += g_bsum[blockIdx.x];
}
__global__ void k_fill(const int* __restrict__ edge) {
    int e = blockIdx.x * blockDim.x + threadIdx.x;
    if (e < NE) {
        int d = edge[NE + e];
        int p = atomicAdd(&g_cur[d], 1);
        g_srclist[g_off[d] + p] = edge[e];
    }
}

// ---------------- gather: z = h + sum h[src], written as bf16 hi/lo planes ----------------
__global__ void k_gather(const float* __restrict__ xin, int first) {
    const float* h = first ? xin : (const float*)g_h;
    int w = (blockIdx.x * blockDim.x + threadIdx.x) >> 5;
    int lane = threadIdx.x & 31;
    if (w >= NN) return;
    int beg = g_off[w], end = g_off[w + 1];
    const float4* hv = (const float4*)h;
    float4 acc = hv[(size_t)w * 32 + lane];
    int e = beg;
    for (; e + 4 <= end; e += 4) {
        int s0 = g_srclist[e],     s1 = g_srclist[e + 1];
        int s2 = g_srclist[e + 2], s3 = g_srclist[e + 3];
        float4 v0 = __ldg(&hv[(size_t)s0 * 32 + lane]);
        float4 v1 = __ldg(&hv[(size_t)s1 * 32 + lane]);
        float4 v2 = __ldg(&hv[(size_t)s2 * 32 + lane]);
        float4 v3 = __ldg(&hv[(size_t)s3 * 32 + lane]);
        acc.x += v0.x + v1.x + v2.x + v3.x;
        acc.y += v0.y + v1.y + v2.y + v3.y;
        acc.z += v0.z + v1.z + v2.z + v3.z;
        acc.w += v0.w + v1.w + v2.w + v3.w;
    }
    for (; e < end; e++) {
        float4 v = __ldg(&hv[(size_t)g_srclist[e] * 32 + lane]);
        acc.x += v.x; acc.y += v.y; acc.z += v.z; acc.w += v.w;
    }
    __nv_bfloat16 h0 = __float2bfloat16(acc.x), h1 = __float2bfloat16(acc.y);
    __nv_bfloat16 h2 = __float2bfloat16(acc.z), h3 = __float2bfloat16(acc.w);
    __nv_bfloat162 hp0 = __halves2bfloat162(h0, h1);
    __nv_bfloat162 hp1 = __halves2bfloat162(h2, h3);
    __nv_bfloat162 lp0 = __floats2bfloat162_rn(acc.x - __bfloat162float(h0), acc.y - __bfloat162float(h1));
    __nv_bfloat162 lp1 = __floats2bfloat162_rn(acc.z - __bfloat162float(h2), acc.w - __bfloat162float(h3));
    ((uint2*)g_zhi)[(size_t)w * 32 + lane] = make_uint2(*(uint32_t*)&hp0, *(uint32_t*)&hp1);
    ((uint2*)g_zlo)[(size_t)w * 32 + lane] = make_uint2(*(uint32_t*)&lp0, *(uint32_t*)&lp1);
}

// ---------------- fused-term warp-tile GEMM (16x64 warp tile, swizzled smem) ----------------
__device__ __forceinline__ void gemm64(
    uint32_t aHi, uint32_t aLo, uint32_t bHi, uint32_t bLo,
    uint32_t arowoff, uint32_t browoff, const uint32_t* PA, const uint32_t* PB,
    float acc[8][4])
{
#pragma unroll
    for (int ks = 0; ks < 8; ks++) {
        uint32_t ka = PA[ks & 3] + (ks >> 2) * 128;
        uint32_t kb = PB[ks & 3] + (ks >> 2) * 128;
        uint32_t ah[4], al[4], bh[8][2], bl[8][2];
        LDSM4(ah[0], ah[1], ah[2], ah[3], aHi + arowoff + ka);
        LDSM4(al[0], al[1], al[2], al[3], aLo + arowoff + ka);
#pragma unroll
        for (int j = 0; j < 4; j++) {
            LDSM4(bh[2 * j][0], bh[2 * j][1], bh[2 * j + 1][0], bh[2 * j + 1][1],
                  bHi + browoff + (uint32_t)j * 4096 + kb);
            LDSM4(bl[2 * j][0], bl[2 * j][1], bl[2 * j + 1][0], bl[2 * j + 1][1],
                  bLo + browoff + (uint32_t)j * 4096 + kb);
        }
#pragma unroll
        for (int nt = 0; nt < 8; nt++) mma_bf16(acc[nt], ah, bh[nt]);
#pragma unroll
        for (int nt = 0; nt < 8; nt++) mma_bf16(acc[nt], ah, bl[nt]);
#pragma unroll
        for (int nt = 0; nt < 8; nt++) mma_bf16(acc[nt], al, bh[nt]);
    }
}

// ---------------- fused 2-layer MLP: 64-row tiles, double-buffered A, pipelined ----------------
__global__ void __launch_bounds__(256, 1) k_mlp(
    int layer, const float* __restrict__ b1, const float* __restrict__ b2,
    int last, float* __restrict__ xoutp)
{
    extern __shared__ __nv_bfloat16 sm[];
    float* outp = last ? xoutp : (float*)g_h;
    uint32_t sb = s2u(sm);

    int tid = threadIdx.x, lane = tid & 31, warp = tid >> 5;
    int wr = warp & 3, wc = warp >> 2;   // warp tile: rows wr*16..+15, cols wc*64..+63

    // ---- prologue: stage weights (swizzled) + first A tile, one cp.async group ----
    {
        const __nv_bfloat16* wl = &g_wsplit[layer][0][0];
        for (int i = tid; i < 8192; i += 256) {
            int mat = i >> 11, rem = i & 2047;
            int r = rem >> 4, c = rem & 15;
            cp16(sb + OFF_W(mat) + swz(r, c), wl + (size_t)i * 8);
        }
    }
    int t0 = blockIdx.x;
    {
        int row0 = t0 * 64;
        for (int i = tid; i < 2048; i += 256) {
            int plane = i >> 10, rem = i & 1023;
            int r = rem >> 4, c = rem & 15;
            const __nv_bfloat16* src = (plane ? g_zlo : g_zhi) + (size_t)(row0 + r) * HD + c * 8;
            cp16(sb + OFF_A(0, plane) + swz(r, c), src);
        }
    }
    cp_commit();

    // bias registers
    float bv1[16], bv2[16];
    int cb = wc * 64 + (lane & 3) * 2;
#pragma unroll
    for (int nt = 0; nt < 8; nt++) {
        bv1[nt * 2]     = __ldg(&b1[cb + nt * 8]);
        bv1[nt * 2 + 1] = __ldg(&b1[cb + nt * 8 + 1]);
        bv2[nt * 2]     = __ldg(&b2[cb + nt * 8]);
        bv2[nt * 2 + 1] = __ldg(&b2[cb + nt * 8 + 1]);
    }

    // per-lane ldmatrix geometry
    int g = lane >> 3, lr = lane & 7;
    uint32_t arowoff = (uint32_t)(wr * 16 + (g & 1) * 8 + lr) * 256;
    uint32_t browoff = (uint32_t)(wc * 64 + (g >> 1) * 8 + lr) * 256;
    uint32_t PA[4], PB[4];
#pragma unroll
    for (int j = 0; j < 4; j++) {
        PA[j] = (uint32_t)((((g >> 1) + 2 * j) ^ lr) << 4);
        PB[j] = (uint32_t)((((g & 1) + 2 * j) ^ lr) << 4);
    }

    int er0 = wr * 16 + (lane >> 2);     // epilogue rows (local)
    int buf = 0;

    for (int t = t0; t < NT64; t += GRID) {
        cp_wait0();
        __syncthreads();                 // A(t) + weights visible

        // prefetch next tile's A into the other buffer (overlaps both GEMMs)
        int tn = t + GRID;
        if (tn < NT64) {
            int row0n = tn * 64;
            for (int i = tid; i < 2048; i += 256) {
                int plane = i >> 10, rem = i & 1023;
                int r = rem >> 4, c = rem & 15;
                const __nv_bfloat16* src = (plane ? g_zlo : g_zhi) + (size_t)(row0n + r) * HD + c * 8;
                cp16(sb + OFF_A(buf ^ 1, plane) + swz(r, c), src);
            }
        }
        cp_commit();

        // ---- GEMM1: acc = A @ W1 (bf16x3 fused) ----
        float acc[8][4];
#pragma unroll
        for (int nt = 0; nt < 8; nt++)
#pragma unroll
            for (int j = 0; j < 4; j++) acc[nt][j] = 0.f;
        gemm64(sb + OFF_A(buf, 0), sb + OFF_A(buf, 1),
               sb + OFF_W(0), sb + OFF_W(1), arowoff, browoff, PA, PB, acc);

        // ---- epilogue1: z1 = relu(acc + b1) -> swizzled z1 planes ----
#pragma unroll
        for (int nt = 0; nt < 8; nt++) {
            int chunk = wc * 8 + nt;
            float v0 = fmaxf(acc[nt][0] + bv1[nt * 2],     0.f);
            float v1 = fmaxf(acc[nt][1] + bv1[nt * 2 + 1], 0.f);
            float v2 = fmaxf(acc[nt][2] + bv1[nt * 2],     0.f);
            float v3 = fmaxf(acc[nt][3] + bv1[nt * 2 + 1], 0.f);
            __nv_bfloat16 h0 = __float2bfloat16(v0), h1 = __float2bfloat16(v1);
            __nv_bfloat16 h2 = __float2bfloat16(v2), h3 = __float2bfloat16(v3);
            __nv_bfloat162 hp0 = __halves2bfloat162(h0, h1);
            __nv_bfloat162 hp1 = __halves2bfloat162(h2, h3);
            __nv_bfloat162 lp0 = __floats2bfloat162_rn(v0 - __bfloat162float(h0), v1 - __bfloat162float(h1));
            __nv_bfloat162 lp1 = __floats2bfloat162_rn(v2 - __bfloat162float(h2), v3 - __bfloat162float(h3));
            uint32_t w4 = (uint32_t)(lane & 3) * 4;
            uint32_t a0 = swz((uint32_t)er0,     (uint32_t)chunk) + w4;
            uint32_t a1 = swz((uint32_t)er0 + 8, (uint32_t)chunk) + w4;
            *(uint32_t*)((char*)sm + OFF_Z1(0) + a0) = *(uint32_t*)&hp0;
            *(uint32_t*)((char*)sm + OFF_Z1(1) + a0) = *(uint32_t*)&lp0;
            *(uint32_t*)((char*)sm + OFF_Z1(0) + a1) = *(uint32_t*)&hp1;
            *(uint32_t*)((char*)sm + OFF_Z1(1) + a1) = *(uint32_t*)&lp1;
        }
        __syncthreads();                 // z1 complete before GEMM2

        // ---- GEMM2: acc = z1 @ W2 ----
#pragma unroll
        for (int nt = 0; nt < 8; nt++)
#pragma unroll
            for (int j = 0; j < 4; j++) acc[nt][j] = 0.f;
        gemm64(sb + OFF_Z1(0), sb + OFF_Z1(1),
               sb + OFF_W(2), sb + OFF_W(3), arowoff, browoff, PA, PB, acc);

        // ---- epilogue2: h = relu(acc + b2) -> global fp32 ----
        int r0 = t * 64 + er0;
        int r1 = r0 + 8;
#pragma unroll
        for (int nt = 0; nt < 8; nt++) {
            int c = wc * 64 + nt * 8 + (lane & 3) * 2;
            if (r0 < NN) {
                float2 v;
                v.x = fmaxf(acc[nt][0] + bv2[nt * 2],     0.f);
                v.y = fmaxf(acc[nt][1] + bv2[nt * 2 + 1], 0.f);
                ((float2*)outp)[(size_t)r0 * 64 + (c >> 1)] = v;
            }
            if (r1 < NN) {
                float2 v;
                v.x = fmaxf(acc[nt][2] + bv2[nt * 2],     0.f);
                v.y = fmaxf(acc[nt][3] + bv2[nt * 2 + 1], 0.f);
                ((float2*)outp)[(size_t)r1 * 64 + (c >> 1)] = v;
            }
        }
        buf ^= 1;
    }
}

// ---------------- mean pool per graph (batch is sorted) ----------------
__global__ void k_pool(const float* __restrict__ xout, const int* __restrict__ batch,
                       float* __restrict__ gout) {
    int b = blockIdx.x, t = threadIdx.x;
    int lo = 0, hi = NN;
    while (lo < hi) { int m = (lo + hi) >> 1; if (batch[m] < b) lo = m + 1; else hi = m; }
    int beg = lo;
    hi = NN;
    while (lo < hi) { int m = (lo + hi) >> 1; if (batch[m] <= b) lo = m + 1; else hi = m; }
    int end = lo;
    float acc = 0.f;
    for (int i = beg; i < end; i++) acc += xout[(size_t)i * HD + t];
    int cnt = end - beg;
    gout[b * HD + t] = acc / (float)(cnt > 0 ? cnt : 1);
}

// ---------------- launch ----------------
extern "C" void kernel_launch(void* const* d_in, const int* in_sizes, int n_in,
                              void* d_out, int out_size)
{
    const float* x   = (const float*)d_in[0];
    const int* edge  = (const int*)d_in[1];
    const int* batch = (const int*)d_in[2];
    const float* W1  = (const float*)d_in[3];
    const float* b1  = (const float*)d_in[4];
    const float* W2  = (const float*)d_in[5];
    const float* b2  = (const float*)d_in[6];
    float* out  = (float*)d_out;
    float* xout = out;
    float* gout = out + (size_t)NN * HD;

    cudaFuncSetAttribute(k_mlp, cudaFuncAttributeMaxDynamicSharedMemorySize, SM_TOTAL);

    void *cntp, *curp;
    cudaGetSymbolAddress(&cntp, g_cnt);
    cudaGetSymbolAddress(&curp, g_cur);

    k_prep_weights<<<(NL * HD * HD + 255) / 256, 256>>>(W1, W2);
    cudaMemsetAsync(cntp, 0, NN * sizeof(int));
    cudaMemsetAsync(curp, 0, NN * sizeof(int));
    k_count<<<(NE + 255) / 256, 256>>>(edge);
    k_scan1<<<SCAN_BLOCKS, 1024>>>();
    k_scan2<<<1, 32>>>();
    k_scan3<<<SCAN_BLOCKS, 1024>>>();
    k_fill<<<(NE + 255) / 256, 256>>>(edge);

    for (int l = 0; l < NL; l++) {
        k_gather<<<(NN * 32 + 255) / 256, 256>>>(x, l == 0 ? 1 : 0);
        k_mlp<<<GRID, 256, SM_TOTAL>>>(l, b1 + (size_t)l * HD, b2 + (size_t)l * HD,
                                       (l == NL - 1) ? 1 : 0, xout);
    }
    k_pool<<<NG, HD>>>(xout, batch, gout);
}